// round 15
// baseline (speedup 1.0000x reference)
#include <cuda_runtime.h>
#include <cstdint>

// Problem constants
#define BB 8
#define DD 256
#define NN 2048
#define HH 4
#define HD 64

// Scratch — __device__ globals per allocation rules
__device__ float g_qi[BB * DD * NN];  // tf32-rounded raw inputs
__device__ float g_ki[BB * DD * NN];
__device__ float g_vi[BB * DD * NN];
__device__ float g_wq[DD * DD];       // tf32-rounded weights
__device__ float g_wk[DD * DD];
__device__ float g_wv[DD * DD];
__device__ float g_wm[DD * DD];
__device__ float g_q[BB * DD * NN];   // Q proj: tf32(0.125*log2e*val)
__device__ float g_k[BB * DD * NN];   // K proj: tf32, paired [b][h][pr][n][e]
__device__ float g_v[BB * DD * NN];   // V proj: tf32, natural layout
__device__ float g_x[BB * DD * NN];   // attention out (tf32-rounded)

__device__ __forceinline__ uint32_t f2tf32(float f) {
    uint32_t u;
    asm("cvt.rna.tf32.f32 %0, %1;" : "=r"(u) : "f"(f));
    return u;
}

__device__ __forceinline__ float ex2f(float f) {
    float r;
    asm("ex2.approx.f32 %0, %1;" : "=f"(r) : "f"(f));
    return r;
}

__device__ __forceinline__ uint32_t smem_u32(const void* p) {
    uint32_t a;
    asm("{ .reg .u64 t; cvta.to.shared.u64 t, %1; cvt.u32.u64 %0, t; }"
        : "=r"(a) : "l"(p));
    return a;
}

__device__ __forceinline__ void cp16(uint32_t saddr, const float* g) {
    uint64_t ga;
    asm("cvta.to.global.u64 %0, %1;" : "=l"(ga) : "l"(g));
    asm volatile("cp.async.ca.shared.global [%0], [%1], 16;"
                 :: "r"(saddr), "l"(ga));
}
#define CP_COMMIT() asm volatile("cp.async.commit_group;" ::: "memory")
#define CP_WAIT0()  asm volatile("cp.async.wait_group 0;" ::: "memory")
#define CP_WAIT1()  asm volatile("cp.async.wait_group 1;" ::: "memory")

// tf32 m16n8k8: D += A*B
__device__ __forceinline__ void mma_tf32(float d[4],
                                         uint32_t a0, uint32_t a1,
                                         uint32_t a2, uint32_t a3,
                                         uint32_t b0, uint32_t b1) {
    asm volatile(
        "mma.sync.aligned.m16n8k8.row.col.f32.tf32.tf32.f32 "
        "{%0,%1,%2,%3}, {%4,%5,%6,%7}, {%8,%9}, {%0,%1,%2,%3};"
        : "+f"(d[0]), "+f"(d[1]), "+f"(d[2]), "+f"(d[3])
        : "r"(a0), "r"(a1), "r"(a2), "r"(a3), "r"(b0), "r"(b1));
}

// ===========================================================================
// Prep: RNA-round inputs (q,k,v) and the four weight matrices to tf32 bits.
// ===========================================================================
__global__ void __launch_bounds__(256) prep_kernel(
    const float* __restrict__ q, const float* __restrict__ k,
    const float* __restrict__ v,
    const float* __restrict__ wq, const float* __restrict__ wk,
    const float* __restrict__ wv, const float* __restrict__ wm)
{
    const int i = blockIdx.x * 256 + threadIdx.x;   // float4 index
    if (i < (BB * DD * NN) / 4) {
        float4 a = ((const float4*)q)[i];
        float4 b = ((const float4*)k)[i];
        float4 c = ((const float4*)v)[i];
        a.x = __uint_as_float(f2tf32(a.x)); a.y = __uint_as_float(f2tf32(a.y));
        a.z = __uint_as_float(f2tf32(a.z)); a.w = __uint_as_float(f2tf32(a.w));
        b.x = __uint_as_float(f2tf32(b.x)); b.y = __uint_as_float(f2tf32(b.y));
        b.z = __uint_as_float(f2tf32(b.z)); b.w = __uint_as_float(f2tf32(b.w));
        c.x = __uint_as_float(f2tf32(c.x)); c.y = __uint_as_float(f2tf32(c.y));
        c.z = __uint_as_float(f2tf32(c.z)); c.w = __uint_as_float(f2tf32(c.w));
        ((float4*)g_qi)[i] = a;
        ((float4*)g_ki)[i] = b;
        ((float4*)g_vi)[i] = c;
    }
    if (i < (DD * DD) / 4) {
        float4 a = ((const float4*)wq)[i];
        float4 b = ((const float4*)wk)[i];
        float4 c = ((const float4*)wv)[i];
        float4 d = ((const float4*)wm)[i];
        a.x = __uint_as_float(f2tf32(a.x)); a.y = __uint_as_float(f2tf32(a.y));
        a.z = __uint_as_float(f2tf32(a.z)); a.w = __uint_as_float(f2tf32(a.w));
        b.x = __uint_as_float(f2tf32(b.x)); b.y = __uint_as_float(f2tf32(b.y));
        b.z = __uint_as_float(f2tf32(b.z)); b.w = __uint_as_float(f2tf32(b.w));
        c.x = __uint_as_float(f2tf32(c.x)); c.y = __uint_as_float(f2tf32(c.y));
        c.z = __uint_as_float(f2tf32(c.z)); c.w = __uint_as_float(f2tf32(c.w));
        d.x = __uint_as_float(f2tf32(d.x)); d.y = __uint_as_float(f2tf32(d.y));
        d.z = __uint_as_float(f2tf32(d.z)); d.w = __uint_as_float(f2tf32(d.w));
        ((float4*)g_wq)[i] = a;
        ((float4*)g_wk)[i] = b;
        ((float4*)g_wv)[i] = c;
        ((float4*)g_wm)[i] = d;
    }
}

// ===========================================================================
// Projection GEMM body: cp.async 3-stage pipeline (wait_group 1), ONE
// barrier per 32-row chunk. Operands pre-rounded (zero cvt in loop).
// 256 threads = 4 rg x 2 cg; 128x128 output tile.
// omode: 0 = plain fp32, 1 = tf32 bits, 2 = tf32(0.125*log2e*val),
//        5 = tf32 bits + K-paired gmem layout [b][h][pr][n][e]
// ===========================================================================
#define PS 136
#define CHW (32 * PS)                    // words per chunk buffer
#define PXO (3 * CHW)                    // X buffers start (3 W buffers first)
#define PROJ_SMEM (6 * CHW * 4)          // 104,448 bytes
#define QSCALE 0.1803368801111446f      // 0.125 * log2(e)

__device__ __forceinline__ void proj_body(
    const float* __restrict__ X, const float* __restrict__ W,
    const float* __restrict__ bias, float* __restrict__ out,
    int omode, int b, float* smf)
{
    uint32_t* smw = (uint32_t*)smf;
    const uint32_t sb = smem_u32(smf);

    const int tid  = threadIdx.x;
    const int warp = tid >> 5;
    const int lane = tid & 31;
    const int j    = lane & 3;
    const int r    = lane >> 2;
    const int rg   = warp & 3;
    const int cg   = warp >> 2;

    const int o0 = blockIdx.y * 128;
    const int n0 = blockIdx.x * 128;
    const float* Xb = X + (size_t)b * DD * NN;

    const int srow = tid >> 3;
    const int sseg = (tid & 7) * 16;
    const uint32_t wdst = sb + (srow * PS + sseg) * 4;
    const uint32_t xdst = sb + (PXO + srow * PS + sseg) * 4;

    // prologue: issue chunks 0 and 1
#pragma unroll
    for (int c0 = 0; c0 < 2; c0++) {
#pragma unroll
        for (int i = 0; i < 4; i++) {
            cp16(wdst + c0 * CHW * 4 + i * 16,
                 W  + (size_t)(c0 * 32 + srow) * DD + o0 + sseg + i * 4);
            cp16(xdst + c0 * CHW * 4 + i * 16,
                 Xb + (size_t)(c0 * 32 + srow) * NN + n0 + sseg + i * 4);
        }
        CP_COMMIT();
    }

    float acc[2][8][4];
#pragma unroll
    for (int mt = 0; mt < 2; mt++)
#pragma unroll
        for (int nc = 0; nc < 8; nc++)
#pragma unroll
            for (int c = 0; c < 4; c++) acc[mt][nc][c] = 0.f;

    int cur = 0;
    for (int ch = 0; ch < 8; ch++) {
        if (ch + 1 < 8) CP_WAIT1(); else CP_WAIT0();
        __syncthreads();   // chunk ch visible; all warps done with buffer being refilled

        if (ch + 2 < 8) {
            int nb = cur + 2; if (nb >= 3) nb -= 3;
            const int d0c = (ch + 2) * 32;
#pragma unroll
            for (int i = 0; i < 4; i++) {
                cp16(wdst + nb * CHW * 4 + i * 16,
                     W  + (size_t)(d0c + srow) * DD + o0 + sseg + i * 4);
                cp16(xdst + nb * CHW * 4 + i * 16,
                     Xb + (size_t)(d0c + srow) * NN + n0 + sseg + i * 4);
            }
            CP_COMMIT();
        }

        const uint32_t* Wt = smw + cur * CHW;
        const uint32_t* Xt = smw + PXO + cur * CHW;

#pragma unroll
        for (int kc = 0; kc < 4; kc++) {
            const int d0 = kc * 8;
            uint32_t a[2][4];
#pragma unroll
            for (int mt = 0; mt < 2; mt++) {
                const int ob = rg * 32 + mt * 16 + r;
                a[mt][0] = Wt[(d0 + j) * PS + ob];
                a[mt][1] = Wt[(d0 + j) * PS + ob + 8];
                a[mt][2] = Wt[(d0 + j + 4) * PS + ob];
                a[mt][3] = Wt[(d0 + j + 4) * PS + ob + 8];
            }
#pragma unroll
            for (int nc = 0; nc < 8; nc++) {
                const int nb = cg * 64 + nc * 8 + r;
                const uint32_t b0 = Xt[(d0 + j) * PS + nb];
                const uint32_t b1 = Xt[(d0 + j + 4) * PS + nb];
                mma_tf32(acc[0][nc], a[0][0], a[0][1], a[0][2], a[0][3], b0, b1);
                mma_tf32(acc[1][nc], a[1][0], a[1][1], a[1][2], a[1][3], b0, b1);
            }
        }
        cur = (cur + 1 == 3) ? 0 : cur + 1;
    }

#pragma unroll
    for (int mt = 0; mt < 2; mt++) {
        const int orow = o0 + rg * 32 + mt * 16 + r;
        const float bi0 = bias[orow];
        const float bi1 = bias[orow + 8];
#pragma unroll
        for (int nc = 0; nc < 8; nc++) {
            float v00 = acc[mt][nc][0] + bi0, v01 = acc[mt][nc][1] + bi0;
            float v10 = acc[mt][nc][2] + bi1, v11 = acc[mt][nc][3] + bi1;
            if (omode == 2) {
                v00 *= QSCALE; v01 *= QSCALE; v10 *= QSCALE; v11 *= QSCALE;
            }
            if (omode >= 1) {
                v00 = __uint_as_float(f2tf32(v00));
                v01 = __uint_as_float(f2tf32(v01));
                v10 = __uint_as_float(f2tf32(v10));
                v11 = __uint_as_float(f2tf32(v11));
            }
            const int ncol = n0 + cg * 64 + nc * 8 + 2 * j;
            if (omode == 5) {
                // K-paired layout: idx = b*DD*NN + h*64*NN + pr*2*NN + n*2 + e
#pragma unroll
                for (int rr = 0; rr < 2; rr++) {
                    const int o = orow + rr * 8;
                    const int h  = o & 3;
                    const int dh = o >> 2;
                    const int pr = ((dh >> 3) << 2) | (dh & 3);
                    const int e  = (dh >> 2) & 1;
                    float* dst = out + (size_t)b * DD * NN
                               + (size_t)h * 64 * NN + (size_t)pr * 2 * NN + e;
                    const float a0 = rr ? v10 : v00;
                    const float a1 = rr ? v11 : v01;
                    dst[(size_t)ncol * 2]       = a0;
                    dst[(size_t)(ncol + 1) * 2] = a1;
                }
            } else {
                float* row0 = out + (size_t)b * DD * NN + (size_t)orow * NN + ncol;
                float* row1 = row0 + 8 * NN;
                *(float2*)row0 = make_float2(v00, v01);
                *(float2*)row1 = make_float2(v10, v11);
            }
        }
    }
}

// Merged Q/K/V projection: z = which*8 + b. 768 CTAs -> 2.6 waves.
__global__ void __launch_bounds__(256, 2) proj_qkv_kernel(
    const float* __restrict__ bq, const float* __restrict__ bk,
    const float* __restrict__ bv)
{
    extern __shared__ float smf[];
    const int zz = blockIdx.z >> 3;
    const int b  = blockIdx.z & 7;
    if (zz == 0)      proj_body(g_qi, g_wq, bq, g_q, 2, b, smf);
    else if (zz == 1) proj_body(g_ki, g_wk, bk, g_k, 5, b, smf);
    else              proj_body(g_vi, g_wv, bv, g_v, 1, b, smf);
}

// Final projection (plain fp32 out), 128-row tiles.
__global__ void __launch_bounds__(256, 2) proj_out_kernel(
    const float* __restrict__ bias, float* __restrict__ out)
{
    extern __shared__ float smf[];
    proj_body(g_x, g_wm, bias, out, 0, blockIdx.z, smf);
}

// ===========================================================================
// Fused attention, QT=256 (512 threads, 16 warps x 16 query rows sharing one
// K/V staging). All-tf32, P register-resident (no cvt: tf32 mma truncates P
// in HW; rowsum on full-precision exp). 3-stage cp.async pipeline, ONE
// barrier per key tile. B-frags via LDS.64 (K paired, V natural). Bare ex2
// (log2e pre-folded). Softmax without max subtraction (scores bounded).
// Smem 107,520 B; 1 CTA/SM; regs <= 128.
// ===========================================================================
#define QT 256
#define KTILE 64
#define NTILES (NN / KTILE)

#define AK2 136
#define AVS 72
#define KBW (32 * AK2)                // 4352 words / K buffer
#define VBW (64 * AVS)                // 4608 words / V buffer
#define OFF_K 0
#define OFF_V (3 * KBW)               // 3 K buffers then 3 V buffers
#define ATTN_SMEM ((OFF_V + 3 * VBW) * 4)   // 107,520 bytes

__global__ void __launch_bounds__(512, 1) attn_mma_kernel(
    const float* __restrict__ Q, const float* __restrict__ K,
    const float* __restrict__ V, float* __restrict__ O)
{
    extern __shared__ float smf[];
    uint32_t* smw = (uint32_t*)smf;
    const uint32_t sb = smem_u32(smf);

    const int tid  = threadIdx.x;
    const int warp = tid >> 5;            // 0..15
    const int lane = tid & 31;
    const int j    = lane & 3;
    const int r    = lane >> 2;

    const int bid = blockIdx.x;
    const int q0  = (bid & 7) * QT;
    const int h   = (bid >> 3) & 3;
    const int b   = bid >> 5;
    const size_t base = (size_t)b * DD * NN + (size_t)h * NN;

    // K staging: thread covers 8 words of one pr-row
    const int kr   = tid >> 4;
    const int kseg = (tid & 15) * 8;
    const float* Kgc = K + (size_t)b * DD * NN + (size_t)h * 64 * NN
                     + (size_t)kr * 2 * NN + kseg;
    const uint32_t kaddr0 = sb + (OFF_K + kr * AK2 + kseg) * 4;
    // V staging: thread covers 8 keys of one dh-row
    const int vr   = tid >> 3;
    const int vseg = (tid & 7) * 8;
    const float* Vgc = V + base + (size_t)vr * HH * NN + vseg;
    const uint32_t vaddr0 = sb + (OFF_V + vr * AVS + vseg) * 4;

    // prologue: issue tiles 0 and 1
#pragma unroll
    for (int t0 = 0; t0 < 2; t0++) {
#pragma unroll
        for (int i = 0; i < 2; i++) {
            cp16(kaddr0 + t0 * KBW * 4 + i * 16, Kgc + t0 * KTILE * 2 + i * 4);
            cp16(vaddr0 + t0 * VBW * 4 + i * 16, Vgc + t0 * KTILE + i * 4);
        }
        CP_COMMIT();
    }

    // Q A-fragments in registers (once)
    const int qrow = warp * 16 + r;
    uint32_t qa[8][4];
    {
        const float* Qg = Q + base + q0 + qrow;
#pragma unroll
        for (int kc = 0; kc < 8; kc++) {
            const float* p0 = Qg + (size_t)(kc * 8 + j) * HH * NN;
            const float* p1 = Qg + (size_t)(kc * 8 + j + 4) * HH * NN;
            qa[kc][0] = __float_as_uint(p0[0]);
            qa[kc][1] = __float_as_uint(p0[8]);
            qa[kc][2] = __float_as_uint(p1[0]);
            qa[kc][3] = __float_as_uint(p1[8]);
        }
    }

    float oacc[8][4];
#pragma unroll
    for (int nc = 0; nc < 8; nc++)
#pragma unroll
        for (int c = 0; c < 4; c++) oacc[nc][c] = 0.f;
    float rsA = 0.f, rsB = 0.f, rsC = 0.f, rsD = 0.f;

    int cur = 0;
    for (int t = 0; t < NTILES; t++) {
        if (t + 1 < NTILES) CP_WAIT1(); else CP_WAIT0();
        __syncthreads();   // tile t visible; refill target buffer drained

        if (t + 2 < NTILES) {
            int nb = cur + 2; if (nb >= 3) nb -= 3;
            const int kn = (t + 2) * KTILE;
#pragma unroll
            for (int i = 0; i < 2; i++) {
                cp16(kaddr0 + nb * KBW * 4 + i * 16, Kgc + kn * 2 + i * 4);
                cp16(vaddr0 + nb * VBW * 4 + i * 16, Vgc + kn + i * 4);
            }
            CP_COMMIT();
        }

        const uint32_t* Kb = smw + OFF_K + cur * KBW;
        const uint32_t* Vb = smw + OFF_V + cur * VBW;

        // ---- S = Q . K^T ----
        float s[8][4];
#pragma unroll
        for (int nc = 0; nc < 8; nc++)
#pragma unroll
            for (int c = 0; c < 4; c++) s[nc][c] = 0.f;

#pragma unroll
        for (int kc = 0; kc < 8; kc++) {
            const int pr = kc * 4 + j;
#pragma unroll
            for (int nc = 0; nc < 8; nc++) {
                const uint2 bb =
                    *(const uint2*)&Kb[pr * AK2 + (nc * 8 + r) * 2];
                mma_tf32(s[nc], qa[kc][0], qa[kc][1], qa[kc][2], qa[kc][3],
                         bb.x, bb.y);
            }
        }

        // exp2 (log2e pre-folded); P stays full fp32 in regs (HW truncates)
#pragma unroll
        for (int nc = 0; nc < 8; nc++) {
            const float e0 = ex2f(s[nc][0]);
            const float e1 = ex2f(s[nc][1]);
            const float e2 = ex2f(s[nc][2]);
            const float e3 = ex2f(s[nc][3]);
            if (nc & 1) { rsB += e0 + e1; rsD += e2 + e3; }
            else        { rsA += e0 + e1; rsC += e2 + e3; }
            s[nc][0] = e0; s[nc][1] = e1; s[nc][2] = e2; s[nc][3] = e3;
        }

        // ---- O += P . V ----
#pragma unroll
        for (int kc = 0; kc < 8; kc++) {
            const uint32_t a0 = __float_as_uint(s[kc][0]);
            const uint32_t a1 = __float_as_uint(s[kc][2]);
            const uint32_t a2 = __float_as_uint(s[kc][1]);
            const uint32_t a3 = __float_as_uint(s[kc][3]);
            const int kk = kc * 8 + 2 * j;
#pragma unroll
            for (int nc = 0; nc < 8; nc++) {
                const uint2 vb =
                    *(const uint2*)&Vb[(nc * 8 + r) * AVS + kk];
                mma_tf32(oacc[nc], a0, a1, a2, a3, vb.x, vb.y);
            }
        }
        cur = (cur + 1 == 3) ? 0 : cur + 1;
    }

    float rs0 = rsA + rsB;
    float rs1 = rsC + rsD;
    rs0 += __shfl_xor_sync(0xffffffffu, rs0, 1);
    rs0 += __shfl_xor_sync(0xffffffffu, rs0, 2);
    rs1 += __shfl_xor_sync(0xffffffffu, rs1, 1);
    rs1 += __shfl_xor_sync(0xffffffffu, rs1, 2);
    const float inv0 = 1.0f / rs0;
    const float inv1 = 1.0f / rs1;

    // Stage normalized O as [q=256][dh] (stride 68), then store tf32-rounded
    __syncthreads();
#pragma unroll
    for (int nc = 0; nc < 8; nc++) {
        const int col = nc * 8 + 2 * j;
        smf[qrow * 68 + col]           = oacc[nc][0] * inv0;
        smf[qrow * 68 + col + 1]       = oacc[nc][1] * inv0;
        smf[(qrow + 8) * 68 + col]     = oacc[nc][2] * inv1;
        smf[(qrow + 8) * 68 + col + 1] = oacc[nc][3] * inv1;
    }
    __syncthreads();
    for (int idx = tid; idx < 64 * QT; idx += 512) {
        const int dh = idx >> 8;
        const int q  = idx & 255;
        O[base + (size_t)dh * HH * NN + q0 + q] =
            __uint_as_float(f2tf32(smf[q * 68 + dh]));
    }
}

// ===========================================================================
// Launch
// ===========================================================================
extern "C" void kernel_launch(void* const* d_in, const int* in_sizes, int n_in,
                              void* d_out, int out_size)
{
    const float* query = (const float*)d_in[0];
    const float* key   = (const float*)d_in[1];
    const float* value = (const float*)d_in[2];
    const float* Wq = (const float*)d_in[3];
    const float* bq = (const float*)d_in[4];
    const float* Wk = (const float*)d_in[5];
    const float* bk = (const float*)d_in[6];
    const float* Wv = (const float*)d_in[7];
    const float* bv = (const float*)d_in[8];
    const float* Wm = (const float*)d_in[9];
    const float* bm = (const float*)d_in[10];
    float* out = (float*)d_out;

    static float *pq = nullptr, *pk = nullptr, *pv = nullptr, *px = nullptr;
    static bool init_done = false;
    if (!init_done) {
        cudaGetSymbolAddress((void**)&pq, g_q);
        cudaGetSymbolAddress((void**)&pk, g_k);
        cudaGetSymbolAddress((void**)&pv, g_v);
        cudaGetSymbolAddress((void**)&px, g_x);
        cudaFuncSetAttribute(attn_mma_kernel,
                             cudaFuncAttributeMaxDynamicSharedMemorySize,
                             ATTN_SMEM);
        cudaFuncSetAttribute(proj_qkv_kernel,
                             cudaFuncAttributeMaxDynamicSharedMemorySize, PROJ_SMEM);
        cudaFuncSetAttribute(proj_out_kernel,
                             cudaFuncAttributeMaxDynamicSharedMemorySize, PROJ_SMEM);
        init_done = true;
    }

    prep_kernel<<<(BB * DD * NN / 4 + 255) / 256, 256>>>(
        query, key, value, Wq, Wk, Wv, Wm);

    dim3 qkvgrid(NN / 128, DD / 128, 3 * BB);   // (16, 2, 24) = 768 CTAs
    proj_qkv_kernel<<<qkvgrid, 256, PROJ_SMEM>>>(bq, bk, bv);

    attn_mma_kernel<<<BB * HH * (NN / QT), 512, ATTN_SMEM>>>(pq, pk, pv, px);

    dim3 ogrid(NN / 128, DD / 128, BB);         // (16, 2, 8) = 256 CTAs
    proj_out_kernel<<<ogrid, 256, PROJ_SMEM>>>(bm, out);
}

// round 16
// speedup vs baseline: 1.0651x; 1.0651x over previous
#include <cuda_runtime.h>
#include <cstdint>

// Problem constants
#define BB 8
#define DD 256
#define NN 2048
#define HH 4
#define HD 64

// Scratch — __device__ globals per allocation rules
__device__ float g_qi[BB * DD * NN];  // tf32-rounded raw inputs
__device__ float g_ki[BB * DD * NN];
__device__ float g_vi[BB * DD * NN];
__device__ float g_wq[DD * DD];       // tf32-rounded weights
__device__ float g_wk[DD * DD];
__device__ float g_wv[DD * DD];
__device__ float g_wm[DD * DD];
__device__ float g_q[BB * DD * NN];   // Q proj: tf32(0.125*log2e*val)
__device__ float g_k[BB * DD * NN];   // K proj: tf32, paired [b][h][pr][n][e]
__device__ float g_v[BB * DD * NN];   // V proj: tf32, natural layout
__device__ float g_x[BB * DD * NN];   // attention out (tf32-rounded)

__device__ __forceinline__ uint32_t f2tf32(float f) {
    uint32_t u;
    asm("cvt.rna.tf32.f32 %0, %1;" : "=r"(u) : "f"(f));
    return u;
}

__device__ __forceinline__ float ex2f(float f) {
    float r;
    asm("ex2.approx.f32 %0, %1;" : "=f"(r) : "f"(f));
    return r;
}

__device__ __forceinline__ uint32_t smem_u32(const void* p) {
    uint32_t a;
    asm("{ .reg .u64 t; cvta.to.shared.u64 t, %1; cvt.u32.u64 %0, t; }"
        : "=r"(a) : "l"(p));
    return a;
}

__device__ __forceinline__ void cp16(uint32_t saddr, const float* g) {
    uint64_t ga;
    asm("cvta.to.global.u64 %0, %1;" : "=l"(ga) : "l"(g));
    asm volatile("cp.async.ca.shared.global [%0], [%1], 16;"
                 :: "r"(saddr), "l"(ga));
}
#define CP_COMMIT() asm volatile("cp.async.commit_group;" ::: "memory")
#define CP_WAIT0()  asm volatile("cp.async.wait_group 0;" ::: "memory")

// tf32 m16n8k8: D += A*B
__device__ __forceinline__ void mma_tf32(float d[4],
                                         uint32_t a0, uint32_t a1,
                                         uint32_t a2, uint32_t a3,
                                         uint32_t b0, uint32_t b1) {
    asm volatile(
        "mma.sync.aligned.m16n8k8.row.col.f32.tf32.tf32.f32 "
        "{%0,%1,%2,%3}, {%4,%5,%6,%7}, {%8,%9}, {%0,%1,%2,%3};"
        : "+f"(d[0]), "+f"(d[1]), "+f"(d[2]), "+f"(d[3])
        : "r"(a0), "r"(a1), "r"(a2), "r"(a3), "r"(b0), "r"(b1));
}

// ===========================================================================
// Prep: RNA-round inputs (q,k,v) and the four weight matrices to tf32 bits.
// ===========================================================================
__global__ void __launch_bounds__(256) prep_kernel(
    const float* __restrict__ q, const float* __restrict__ k,
    const float* __restrict__ v,
    const float* __restrict__ wq, const float* __restrict__ wk,
    const float* __restrict__ wv, const float* __restrict__ wm)
{
    const int i = blockIdx.x * 256 + threadIdx.x;   // float4 index
    if (i < (BB * DD * NN) / 4) {
        float4 a = ((const float4*)q)[i];
        float4 b = ((const float4*)k)[i];
        float4 c = ((const float4*)v)[i];
        a.x = __uint_as_float(f2tf32(a.x)); a.y = __uint_as_float(f2tf32(a.y));
        a.z = __uint_as_float(f2tf32(a.z)); a.w = __uint_as_float(f2tf32(a.w));
        b.x = __uint_as_float(f2tf32(b.x)); b.y = __uint_as_float(f2tf32(b.y));
        b.z = __uint_as_float(f2tf32(b.z)); b.w = __uint_as_float(f2tf32(b.w));
        c.x = __uint_as_float(f2tf32(c.x)); c.y = __uint_as_float(f2tf32(c.y));
        c.z = __uint_as_float(f2tf32(c.z)); c.w = __uint_as_float(f2tf32(c.w));
        ((float4*)g_qi)[i] = a;
        ((float4*)g_ki)[i] = b;
        ((float4*)g_vi)[i] = c;
    }
    if (i < (DD * DD) / 4) {
        float4 a = ((const float4*)wq)[i];
        float4 b = ((const float4*)wk)[i];
        float4 c = ((const float4*)wv)[i];
        float4 d = ((const float4*)wm)[i];
        a.x = __uint_as_float(f2tf32(a.x)); a.y = __uint_as_float(f2tf32(a.y));
        a.z = __uint_as_float(f2tf32(a.z)); a.w = __uint_as_float(f2tf32(a.w));
        b.x = __uint_as_float(f2tf32(b.x)); b.y = __uint_as_float(f2tf32(b.y));
        b.z = __uint_as_float(f2tf32(b.z)); b.w = __uint_as_float(f2tf32(b.w));
        c.x = __uint_as_float(f2tf32(c.x)); c.y = __uint_as_float(f2tf32(c.y));
        c.z = __uint_as_float(f2tf32(c.z)); c.w = __uint_as_float(f2tf32(c.w));
        d.x = __uint_as_float(f2tf32(d.x)); d.y = __uint_as_float(f2tf32(d.y));
        d.z = __uint_as_float(f2tf32(d.z)); d.w = __uint_as_float(f2tf32(d.w));
        ((float4*)g_wq)[i] = a;
        ((float4*)g_wk)[i] = b;
        ((float4*)g_wv)[i] = c;
        ((float4*)g_wm)[i] = d;
    }
}

// ===========================================================================
// Projection GEMM body (R14 2-stage cp.async pipeline). Operands pre-rounded
// -> zero cvt in loop. 256 threads = 4 rg x 2 cg; 128x128 output tile;
// 32-row double-buffered chunks.
// omode: 0 = plain fp32, 1 = tf32 bits, 2 = tf32(0.125*log2e*val),
//        5 = tf32 bits + K-paired gmem layout [b][h][pr][n][e]
// ===========================================================================
#define PS 136
#define CHW (32 * PS)
#define PXO (2 * CHW)
#define PROJ_SMEM (4 * CHW * 4)          // 69,632 bytes
#define QSCALE 0.1803368801111446f      // 0.125 * log2(e)

__device__ __forceinline__ void proj_body(
    const float* __restrict__ X, const float* __restrict__ W,
    const float* __restrict__ bias, float* __restrict__ out,
    int omode, int b, float* smf)
{
    uint32_t* smw = (uint32_t*)smf;
    const uint32_t sb = smem_u32(smf);

    const int tid  = threadIdx.x;
    const int warp = tid >> 5;
    const int lane = tid & 31;
    const int j    = lane & 3;
    const int r    = lane >> 2;
    const int rg   = warp & 3;
    const int cg   = warp >> 2;

    const int o0 = blockIdx.y * 128;
    const int n0 = blockIdx.x * 128;
    const float* Xb = X + (size_t)b * DD * NN;

    const int srow = tid >> 3;
    const int sseg = (tid & 7) * 16;
    const uint32_t wdst = sb + (srow * PS + sseg) * 4;
    const uint32_t xdst = sb + (PXO + srow * PS + sseg) * 4;

#pragma unroll
    for (int i = 0; i < 4; i++) {
        cp16(wdst + i * 16, W  + (size_t)srow * DD + o0 + sseg + i * 4);
        cp16(xdst + i * 16, Xb + (size_t)srow * NN + n0 + sseg + i * 4);
    }
    CP_COMMIT();

    float acc[2][8][4];
#pragma unroll
    for (int mt = 0; mt < 2; mt++)
#pragma unroll
        for (int nc = 0; nc < 8; nc++)
#pragma unroll
            for (int c = 0; c < 4; c++) acc[mt][nc][c] = 0.f;

    for (int ch = 0; ch < 8; ch++) {
        const int cur = ch & 1;
        CP_WAIT0();
        __syncthreads();

        if (ch + 1 < 8) {
            const int nxt = (ch + 1) & 1;
            const int d0c = (ch + 1) * 32;
#pragma unroll
            for (int i = 0; i < 4; i++) {
                cp16(wdst + nxt * CHW * 4 + i * 16,
                     W  + (size_t)(d0c + srow) * DD + o0 + sseg + i * 4);
                cp16(xdst + nxt * CHW * 4 + i * 16,
                     Xb + (size_t)(d0c + srow) * NN + n0 + sseg + i * 4);
            }
            CP_COMMIT();
        }

        const uint32_t* Wt = smw + cur * CHW;
        const uint32_t* Xt = smw + PXO + cur * CHW;

#pragma unroll
        for (int kc = 0; kc < 4; kc++) {
            const int d0 = kc * 8;
            uint32_t a[2][4];
#pragma unroll
            for (int mt = 0; mt < 2; mt++) {
                const int ob = rg * 32 + mt * 16 + r;
                a[mt][0] = Wt[(d0 + j) * PS + ob];
                a[mt][1] = Wt[(d0 + j) * PS + ob + 8];
                a[mt][2] = Wt[(d0 + j + 4) * PS + ob];
                a[mt][3] = Wt[(d0 + j + 4) * PS + ob + 8];
            }
#pragma unroll
            for (int nc = 0; nc < 8; nc++) {
                const int nb = cg * 64 + nc * 8 + r;
                const uint32_t b0 = Xt[(d0 + j) * PS + nb];
                const uint32_t b1 = Xt[(d0 + j + 4) * PS + nb];
                mma_tf32(acc[0][nc], a[0][0], a[0][1], a[0][2], a[0][3], b0, b1);
                mma_tf32(acc[1][nc], a[1][0], a[1][1], a[1][2], a[1][3], b0, b1);
            }
        }
        __syncthreads();
    }

#pragma unroll
    for (int mt = 0; mt < 2; mt++) {
        const int orow = o0 + rg * 32 + mt * 16 + r;
        const float bi0 = bias[orow];
        const float bi1 = bias[orow + 8];
#pragma unroll
        for (int nc = 0; nc < 8; nc++) {
            float v00 = acc[mt][nc][0] + bi0, v01 = acc[mt][nc][1] + bi0;
            float v10 = acc[mt][nc][2] + bi1, v11 = acc[mt][nc][3] + bi1;
            if (omode == 2) {
                v00 *= QSCALE; v01 *= QSCALE; v10 *= QSCALE; v11 *= QSCALE;
            }
            if (omode >= 1) {
                v00 = __uint_as_float(f2tf32(v00));
                v01 = __uint_as_float(f2tf32(v01));
                v10 = __uint_as_float(f2tf32(v10));
                v11 = __uint_as_float(f2tf32(v11));
            }
            const int ncol = n0 + cg * 64 + nc * 8 + 2 * j;
            if (omode == 5) {
                // K-paired layout: idx = b*DD*NN + h*64*NN + pr*2*NN + n*2 + e
#pragma unroll
                for (int rr = 0; rr < 2; rr++) {
                    const int o = orow + rr * 8;
                    const int h  = o & 3;
                    const int dh = o >> 2;
                    const int pr = ((dh >> 3) << 2) | (dh & 3);
                    const int e  = (dh >> 2) & 1;
                    float* dst = out + (size_t)b * DD * NN
                               + (size_t)h * 64 * NN + (size_t)pr * 2 * NN + e;
                    const float a0 = rr ? v10 : v00;
                    const float a1 = rr ? v11 : v01;
                    dst[(size_t)ncol * 2]       = a0;
                    dst[(size_t)(ncol + 1) * 2] = a1;
                }
            } else {
                float* row0 = out + (size_t)b * DD * NN + (size_t)orow * NN + ncol;
                float* row1 = row0 + 8 * NN;
                *(float2*)row0 = make_float2(v00, v01);
                *(float2*)row1 = make_float2(v10, v11);
            }
        }
    }
}

// Merged Q/K/V projection: z = which*8 + b. 768 CTAs -> 2.6 waves.
__global__ void __launch_bounds__(256, 2) proj_qkv_kernel(
    const float* __restrict__ bq, const float* __restrict__ bk,
    const float* __restrict__ bv)
{
    extern __shared__ float smf[];
    const int zz = blockIdx.z >> 3;
    const int b  = blockIdx.z & 7;
    if (zz == 0)      proj_body(g_qi, g_wq, bq, g_q, 2, b, smf);
    else if (zz == 1) proj_body(g_ki, g_wk, bk, g_k, 5, b, smf);
    else              proj_body(g_vi, g_wv, bv, g_v, 1, b, smf);
}

// Final projection (plain fp32 out), 128-row tiles.
__global__ void __launch_bounds__(256, 2) proj_out_kernel(
    const float* __restrict__ bias, float* __restrict__ out)
{
    extern __shared__ float smf[];
    proj_body(g_x, g_wm, bias, out, 0, blockIdx.z, smf);
}

// ===========================================================================
// Fused attention, QT=256 (R14 config): one 512-thread CTA per
// (b, h, 256-query tile); 16 warps x 16 query rows share one K/V staging.
// All-tf32 MMAs; P kept full-fp32 in registers (tf32 mma truncates in HW;
// rowsum on full-precision exp — R15-validated, rel_err 6.3e-4).
// 2-stage cp.async double buffer (R14-proven). B-frags via LDS.64
// (K paired layout, V natural). Bare ex2 (log2e pre-folded).
// Softmax without max subtraction (scores bounded; exact math).
// Smem 71,680 B; 1 CTA/SM; regs <= 128.
// ===========================================================================
#define QT 256
#define KTILE 64
#define NTILES (NN / KTILE)

#define AK2 136
#define AVS 72
#define KBW (32 * AK2)
#define VBW (64 * AVS)
#define OFF_K 0
#define OFF_V (2 * KBW)
#define ATTN_SMEM ((OFF_V + 2 * VBW) * 4)   // 71,680 bytes

__global__ void __launch_bounds__(512, 1) attn_mma_kernel(
    const float* __restrict__ Q, const float* __restrict__ K,
    const float* __restrict__ V, float* __restrict__ O)
{
    extern __shared__ float smf[];
    uint32_t* smw = (uint32_t*)smf;
    const uint32_t sb = smem_u32(smf);

    const int tid  = threadIdx.x;
    const int warp = tid >> 5;            // 0..15
    const int lane = tid & 31;
    const int j    = lane & 3;
    const int r    = lane >> 2;

    const int bid = blockIdx.x;
    const int q0  = (bid & 7) * QT;
    const int h   = (bid >> 3) & 3;
    const int b   = bid >> 5;
    const size_t base = (size_t)b * DD * NN + (size_t)h * NN;

    // K staging: thread covers 8 words of one pr-row
    const int kr   = tid >> 4;
    const int kseg = (tid & 15) * 8;
    const float* Kgc = K + (size_t)b * DD * NN + (size_t)h * 64 * NN
                     + (size_t)kr * 2 * NN + kseg;
    const uint32_t kaddr0 = sb + (OFF_K + kr * AK2 + kseg) * 4;
    // V staging: thread covers 8 keys of one dh-row
    const int vr   = tid >> 3;
    const int vseg = (tid & 7) * 8;
    const float* Vgc = V + base + (size_t)vr * HH * NN + vseg;
    const uint32_t vaddr0 = sb + (OFF_V + vr * AVS + vseg) * 4;

#pragma unroll
    for (int i = 0; i < 2; i++) {
        cp16(kaddr0 + i * 16, Kgc + i * 4);
        cp16(vaddr0 + i * 16, Vgc + i * 4);
    }
    CP_COMMIT();

    // Q A-fragments in registers (once)
    const int qrow = warp * 16 + r;
    uint32_t qa[8][4];
    {
        const float* Qg = Q + base + q0 + qrow;
#pragma unroll
        for (int kc = 0; kc < 8; kc++) {
            const float* p0 = Qg + (size_t)(kc * 8 + j) * HH * NN;
            const float* p1 = Qg + (size_t)(kc * 8 + j + 4) * HH * NN;
            qa[kc][0] = __float_as_uint(p0[0]);
            qa[kc][1] = __float_as_uint(p0[8]);
            qa[kc][2] = __float_as_uint(p1[0]);
            qa[kc][3] = __float_as_uint(p1[8]);
        }
    }

    float oacc[8][4];
#pragma unroll
    for (int nc = 0; nc < 8; nc++)
#pragma unroll
        for (int c = 0; c < 4; c++) oacc[nc][c] = 0.f;
    float rsA = 0.f, rsB = 0.f, rsC = 0.f, rsD = 0.f;

    for (int t = 0; t < NTILES; t++) {
        const int cur = t & 1;

        CP_WAIT0();
        __syncthreads();

        if (t + 1 < NTILES) {
            const int nxt = (t + 1) & 1;
            const int kn = (t + 1) * KTILE;
#pragma unroll
            for (int i = 0; i < 2; i++) {
                cp16(kaddr0 + (nxt * KBW) * 4 + i * 16, Kgc + kn * 2 + i * 4);
                cp16(vaddr0 + (nxt * VBW) * 4 + i * 16, Vgc + kn + i * 4);
            }
            CP_COMMIT();
        }

        const uint32_t* Kb = smw + OFF_K + cur * KBW;
        const uint32_t* Vb = smw + OFF_V + cur * VBW;

        // ---- S = Q . K^T ----
        float s[8][4];
#pragma unroll
        for (int nc = 0; nc < 8; nc++)
#pragma unroll
            for (int c = 0; c < 4; c++) s[nc][c] = 0.f;

#pragma unroll
        for (int kc = 0; kc < 8; kc++) {
            const int pr = kc * 4 + j;
#pragma unroll
            for (int nc = 0; nc < 8; nc++) {
                const uint2 bb =
                    *(const uint2*)&Kb[pr * AK2 + (nc * 8 + r) * 2];
                mma_tf32(s[nc], qa[kc][0], qa[kc][1], qa[kc][2], qa[kc][3],
                         bb.x, bb.y);
            }
        }

        // exp2 (log2e pre-folded); P stays full fp32 in regs (HW truncates)
#pragma unroll
        for (int nc = 0; nc < 8; nc++) {
            const float e0 = ex2f(s[nc][0]);
            const float e1 = ex2f(s[nc][1]);
            const float e2 = ex2f(s[nc][2]);
            const float e3 = ex2f(s[nc][3]);
            if (nc & 1) { rsB += e0 + e1; rsD += e2 + e3; }
            else        { rsA += e0 + e1; rsC += e2 + e3; }
            s[nc][0] = e0; s[nc][1] = e1; s[nc][2] = e2; s[nc][3] = e3;
        }

        // ---- O += P . V ----
#pragma unroll
        for (int kc = 0; kc < 8; kc++) {
            const uint32_t a0 = __float_as_uint(s[kc][0]);
            const uint32_t a1 = __float_as_uint(s[kc][2]);
            const uint32_t a2 = __float_as_uint(s[kc][1]);
            const uint32_t a3 = __float_as_uint(s[kc][3]);
            const int kk = kc * 8 + 2 * j;
#pragma unroll
            for (int nc = 0; nc < 8; nc++) {
                const uint2 vb =
                    *(const uint2*)&Vb[(nc * 8 + r) * AVS + kk];
                mma_tf32(oacc[nc], a0, a1, a2, a3, vb.x, vb.y);
            }
        }
    }

    float rs0 = rsA + rsB;
    float rs1 = rsC + rsD;
    rs0 += __shfl_xor_sync(0xffffffffu, rs0, 1);
    rs0 += __shfl_xor_sync(0xffffffffu, rs0, 2);
    rs1 += __shfl_xor_sync(0xffffffffu, rs1, 1);
    rs1 += __shfl_xor_sync(0xffffffffu, rs1, 2);
    const float inv0 = 1.0f / rs0;
    const float inv1 = 1.0f / rs1;

    // Stage normalized O as [q=256][dh] (stride 68), then store tf32-rounded
    __syncthreads();
#pragma unroll
    for (int nc = 0; nc < 8; nc++) {
        const int col = nc * 8 + 2 * j;
        smf[qrow * 68 + col]           = oacc[nc][0] * inv0;
        smf[qrow * 68 + col + 1]       = oacc[nc][1] * inv0;
        smf[(qrow + 8) * 68 + col]     = oacc[nc][2] * inv1;
        smf[(qrow + 8) * 68 + col + 1] = oacc[nc][3] * inv1;
    }
    __syncthreads();
    for (int idx = tid; idx < 64 * QT; idx += 512) {
        const int dh = idx >> 8;
        const int q  = idx & 255;
        O[base + (size_t)dh * HH * NN + q0 + q] =
            __uint_as_float(f2tf32(smf[q * 68 + dh]));
    }
}

// ===========================================================================
// Launch
// ===========================================================================
extern "C" void kernel_launch(void* const* d_in, const int* in_sizes, int n_in,
                              void* d_out, int out_size)
{
    const float* query = (const float*)d_in[0];
    const float* key   = (const float*)d_in[1];
    const float* value = (const float*)d_in[2];
    const float* Wq = (const float*)d_in[3];
    const float* bq = (const float*)d_in[4];
    const float* Wk = (const float*)d_in[5];
    const float* bk = (const float*)d_in[6];
    const float* Wv = (const float*)d_in[7];
    const float* bv = (const float*)d_in[8];
    const float* Wm = (const float*)d_in[9];
    const float* bm = (const float*)d_in[10];
    float* out = (float*)d_out;

    static float *pq = nullptr, *pk = nullptr, *pv = nullptr, *px = nullptr;
    static bool init_done = false;
    if (!init_done) {
        cudaGetSymbolAddress((void**)&pq, g_q);
        cudaGetSymbolAddress((void**)&pk, g_k);
        cudaGetSymbolAddress((void**)&pv, g_v);
        cudaGetSymbolAddress((void**)&px, g_x);
        cudaFuncSetAttribute(attn_mma_kernel,
                             cudaFuncAttributeMaxDynamicSharedMemorySize,
                             ATTN_SMEM);
        cudaFuncSetAttribute(proj_qkv_kernel,
                             cudaFuncAttributeMaxDynamicSharedMemorySize, PROJ_SMEM);
        cudaFuncSetAttribute(proj_out_kernel,
                             cudaFuncAttributeMaxDynamicSharedMemorySize, PROJ_SMEM);
        init_done = true;
    }

    prep_kernel<<<(BB * DD * NN / 4 + 255) / 256, 256>>>(
        query, key, value, Wq, Wk, Wv, Wm);

    dim3 qkvgrid(NN / 128, DD / 128, 3 * BB);   // (16, 2, 24) = 768 CTAs
    proj_qkv_kernel<<<qkvgrid, 256, PROJ_SMEM>>>(bq, bk, bv);

    attn_mma_kernel<<<BB * HH * (NN / QT), 512, ATTN_SMEM>>>(pq, pk, pv, px);

    dim3 ogrid(NN / 128, DD / 128, BB);         // (16, 2, 8) = 256 CTAs
    proj_out_kernel<<<ogrid, 256, PROJ_SMEM>>>(bm, out);
}

// round 17
// speedup vs baseline: 1.0699x; 1.0046x over previous
#include <cuda_runtime.h>
#include <cstdint>

// Problem constants
#define BB 8
#define DD 256
#define NN 2048
#define HH 4
#define HD 64

// Scratch — __device__ globals per allocation rules
__device__ float g_qi[BB * DD * NN];  // tf32-rounded raw inputs
__device__ float g_ki[BB * DD * NN];
__device__ float g_vi[BB * DD * NN];
__device__ float g_wq[DD * DD];       // tf32-rounded weights
__device__ float g_wk[DD * DD];
__device__ float g_wv[DD * DD];
__device__ float g_wm[DD * DD];
__device__ float g_q[BB * DD * NN];   // Q proj: tf32(0.125*log2e*val)
__device__ float g_k[BB * DD * NN];   // K proj: tf32, paired [b][h][pr][n][e]
__device__ float g_v[BB * DD * NN];   // V proj: tf32, natural layout
__device__ float g_x[BB * DD * NN];   // attention out (tf32-rounded)

__device__ __forceinline__ uint32_t f2tf32(float f) {
    uint32_t u;
    asm("cvt.rna.tf32.f32 %0, %1;" : "=r"(u) : "f"(f));
    return u;
}

__device__ __forceinline__ float ex2f(float f) {
    float r;
    asm("ex2.approx.f32 %0, %1;" : "=f"(r) : "f"(f));
    return r;
}

__device__ __forceinline__ uint32_t smem_u32(const void* p) {
    uint32_t a;
    asm("{ .reg .u64 t; cvta.to.shared.u64 t, %1; cvt.u32.u64 %0, t; }"
        : "=r"(a) : "l"(p));
    return a;
}

__device__ __forceinline__ void cp16(uint32_t saddr, const float* g) {
    uint64_t ga;
    asm("cvta.to.global.u64 %0, %1;" : "=l"(ga) : "l"(g));
    asm volatile("cp.async.ca.shared.global [%0], [%1], 16;"
                 :: "r"(saddr), "l"(ga));
}
#define CP_COMMIT() asm volatile("cp.async.commit_group;" ::: "memory")
#define CP_WAIT0()  asm volatile("cp.async.wait_group 0;" ::: "memory")

// tf32 m16n8k8: D += A*B
__device__ __forceinline__ void mma_tf32(float d[4],
                                         uint32_t a0, uint32_t a1,
                                         uint32_t a2, uint32_t a3,
                                         uint32_t b0, uint32_t b1) {
    asm volatile(
        "mma.sync.aligned.m16n8k8.row.col.f32.tf32.tf32.f32 "
        "{%0,%1,%2,%3}, {%4,%5,%6,%7}, {%8,%9}, {%0,%1,%2,%3};"
        : "+f"(d[0]), "+f"(d[1]), "+f"(d[2]), "+f"(d[3])
        : "r"(a0), "r"(a1), "r"(a2), "r"(a3), "r"(b0), "r"(b1));
}

// ===========================================================================
// Prep: RNA-round inputs (q,k,v) and the four weight matrices to tf32 bits.
// ===========================================================================
__global__ void __launch_bounds__(256) prep_kernel(
    const float* __restrict__ q, const float* __restrict__ k,
    const float* __restrict__ v,
    const float* __restrict__ wq, const float* __restrict__ wk,
    const float* __restrict__ wv, const float* __restrict__ wm)
{
    const int i = blockIdx.x * 256 + threadIdx.x;   // float4 index
    if (i < (BB * DD * NN) / 4) {
        float4 a = ((const float4*)q)[i];
        float4 b = ((const float4*)k)[i];
        float4 c = ((const float4*)v)[i];
        a.x = __uint_as_float(f2tf32(a.x)); a.y = __uint_as_float(f2tf32(a.y));
        a.z = __uint_as_float(f2tf32(a.z)); a.w = __uint_as_float(f2tf32(a.w));
        b.x = __uint_as_float(f2tf32(b.x)); b.y = __uint_as_float(f2tf32(b.y));
        b.z = __uint_as_float(f2tf32(b.z)); b.w = __uint_as_float(f2tf32(b.w));
        c.x = __uint_as_float(f2tf32(c.x)); c.y = __uint_as_float(f2tf32(c.y));
        c.z = __uint_as_float(f2tf32(c.z)); c.w = __uint_as_float(f2tf32(c.w));
        ((float4*)g_qi)[i] = a;
        ((float4*)g_ki)[i] = b;
        ((float4*)g_vi)[i] = c;
    }
    if (i < (DD * DD) / 4) {
        float4 a = ((const float4*)wq)[i];
        float4 b = ((const float4*)wk)[i];
        float4 c = ((const float4*)wv)[i];
        float4 d = ((const float4*)wm)[i];
        a.x = __uint_as_float(f2tf32(a.x)); a.y = __uint_as_float(f2tf32(a.y));
        a.z = __uint_as_float(f2tf32(a.z)); a.w = __uint_as_float(f2tf32(a.w));
        b.x = __uint_as_float(f2tf32(b.x)); b.y = __uint_as_float(f2tf32(b.y));
        b.z = __uint_as_float(f2tf32(b.z)); b.w = __uint_as_float(f2tf32(b.w));
        c.x = __uint_as_float(f2tf32(c.x)); c.y = __uint_as_float(f2tf32(c.y));
        c.z = __uint_as_float(f2tf32(c.z)); c.w = __uint_as_float(f2tf32(c.w));
        d.x = __uint_as_float(f2tf32(d.x)); d.y = __uint_as_float(f2tf32(d.y));
        d.z = __uint_as_float(f2tf32(d.z)); d.w = __uint_as_float(f2tf32(d.w));
        ((float4*)g_wq)[i] = a;
        ((float4*)g_wk)[i] = b;
        ((float4*)g_wv)[i] = c;
        ((float4*)g_wm)[i] = d;
    }
}

// ===========================================================================
// Projection GEMM body (R14 2-stage cp.async pipeline, PROVEN). Operands
// pre-rounded -> zero cvt in loop. 256 threads = 4 rg x 2 cg; 128x128 tile.
// omode: 0 = plain fp32, 1 = tf32 bits, 2 = tf32(0.125*log2e*val),
//        5 = tf32 bits + K-paired gmem layout [b][h][pr][n][e]
// ===========================================================================
#define PS 136
#define CHW (32 * PS)
#define PXO (2 * CHW)
#define PROJ_SMEM (4 * CHW * 4)          // 69,632 bytes
#define QSCALE 0.1803368801111446f      // 0.125 * log2(e)

__device__ __forceinline__ void proj_body(
    const float* __restrict__ X, const float* __restrict__ W,
    const float* __restrict__ bias, float* __restrict__ out,
    int omode, int b, float* smf)
{
    uint32_t* smw = (uint32_t*)smf;
    const uint32_t sb = smem_u32(smf);

    const int tid  = threadIdx.x;
    const int warp = tid >> 5;
    const int lane = tid & 31;
    const int j    = lane & 3;
    const int r    = lane >> 2;
    const int rg   = warp & 3;
    const int cg   = warp >> 2;

    const int o0 = blockIdx.y * 128;
    const int n0 = blockIdx.x * 128;
    const float* Xb = X + (size_t)b * DD * NN;

    const int srow = tid >> 3;
    const int sseg = (tid & 7) * 16;
    const uint32_t wdst = sb + (srow * PS + sseg) * 4;
    const uint32_t xdst = sb + (PXO + srow * PS + sseg) * 4;

#pragma unroll
    for (int i = 0; i < 4; i++) {
        cp16(wdst + i * 16, W  + (size_t)srow * DD + o0 + sseg + i * 4);
        cp16(xdst + i * 16, Xb + (size_t)srow * NN + n0 + sseg + i * 4);
    }
    CP_COMMIT();

    float acc[2][8][4];
#pragma unroll
    for (int mt = 0; mt < 2; mt++)
#pragma unroll
        for (int nc = 0; nc < 8; nc++)
#pragma unroll
            for (int c = 0; c < 4; c++) acc[mt][nc][c] = 0.f;

    for (int ch = 0; ch < 8; ch++) {
        const int cur = ch & 1;
        CP_WAIT0();
        __syncthreads();

        if (ch + 1 < 8) {
            const int nxt = (ch + 1) & 1;
            const int d0c = (ch + 1) * 32;
#pragma unroll
            for (int i = 0; i < 4; i++) {
                cp16(wdst + nxt * CHW * 4 + i * 16,
                     W  + (size_t)(d0c + srow) * DD + o0 + sseg + i * 4);
                cp16(xdst + nxt * CHW * 4 + i * 16,
                     Xb + (size_t)(d0c + srow) * NN + n0 + sseg + i * 4);
            }
            CP_COMMIT();
        }

        const uint32_t* Wt = smw + cur * CHW;
        const uint32_t* Xt = smw + PXO + cur * CHW;

#pragma unroll
        for (int kc = 0; kc < 4; kc++) {
            const int d0 = kc * 8;
            uint32_t a[2][4];
#pragma unroll
            for (int mt = 0; mt < 2; mt++) {
                const int ob = rg * 32 + mt * 16 + r;
                a[mt][0] = Wt[(d0 + j) * PS + ob];
                a[mt][1] = Wt[(d0 + j) * PS + ob + 8];
                a[mt][2] = Wt[(d0 + j + 4) * PS + ob];
                a[mt][3] = Wt[(d0 + j + 4) * PS + ob + 8];
            }
#pragma unroll
            for (int nc = 0; nc < 8; nc++) {
                const int nb = cg * 64 + nc * 8 + r;
                const uint32_t b0 = Xt[(d0 + j) * PS + nb];
                const uint32_t b1 = Xt[(d0 + j + 4) * PS + nb];
                mma_tf32(acc[0][nc], a[0][0], a[0][1], a[0][2], a[0][3], b0, b1);
                mma_tf32(acc[1][nc], a[1][0], a[1][1], a[1][2], a[1][3], b0, b1);
            }
        }
        __syncthreads();
    }

#pragma unroll
    for (int mt = 0; mt < 2; mt++) {
        const int orow = o0 + rg * 32 + mt * 16 + r;
        const float bi0 = bias[orow];
        const float bi1 = bias[orow + 8];
#pragma unroll
        for (int nc = 0; nc < 8; nc++) {
            float v00 = acc[mt][nc][0] + bi0, v01 = acc[mt][nc][1] + bi0;
            float v10 = acc[mt][nc][2] + bi1, v11 = acc[mt][nc][3] + bi1;
            if (omode == 2) {
                v00 *= QSCALE; v01 *= QSCALE; v10 *= QSCALE; v11 *= QSCALE;
            }
            if (omode >= 1) {
                v00 = __uint_as_float(f2tf32(v00));
                v01 = __uint_as_float(f2tf32(v01));
                v10 = __uint_as_float(f2tf32(v10));
                v11 = __uint_as_float(f2tf32(v11));
            }
            const int ncol = n0 + cg * 64 + nc * 8 + 2 * j;
            if (omode == 5) {
                // K-paired layout: idx = b*DD*NN + h*64*NN + pr*2*NN + n*2 + e
#pragma unroll
                for (int rr = 0; rr < 2; rr++) {
                    const int o = orow + rr * 8;
                    const int h  = o & 3;
                    const int dh = o >> 2;
                    const int pr = ((dh >> 3) << 2) | (dh & 3);
                    const int e  = (dh >> 2) & 1;
                    float* dst = out + (size_t)b * DD * NN
                               + (size_t)h * 64 * NN + (size_t)pr * 2 * NN + e;
                    const float a0 = rr ? v10 : v00;
                    const float a1 = rr ? v11 : v01;
                    dst[(size_t)ncol * 2]       = a0;
                    dst[(size_t)(ncol + 1) * 2] = a1;
                }
            } else {
                float* row0 = out + (size_t)b * DD * NN + (size_t)orow * NN + ncol;
                float* row1 = row0 + 8 * NN;
                *(float2*)row0 = make_float2(v00, v01);
                *(float2*)row1 = make_float2(v10, v11);
            }
        }
    }
}

// Merged Q/K/V projection: z = which*8 + b. 768 CTAs -> 2.6 waves.
__global__ void __launch_bounds__(256, 2) proj_qkv_kernel(
    const float* __restrict__ bq, const float* __restrict__ bk,
    const float* __restrict__ bv)
{
    extern __shared__ float smf[];
    const int zz = blockIdx.z >> 3;
    const int b  = blockIdx.z & 7;
    if (zz == 0)      proj_body(g_qi, g_wq, bq, g_q, 2, b, smf);
    else if (zz == 1) proj_body(g_ki, g_wk, bk, g_k, 5, b, smf);
    else              proj_body(g_vi, g_wv, bv, g_v, 1, b, smf);
}

// Final projection (plain fp32 out), 128-row tiles.
__global__ void __launch_bounds__(256, 2) proj_out_kernel(
    const float* __restrict__ bias, float* __restrict__ out)
{
    extern __shared__ float smf[];
    proj_body(g_x, g_wm, bias, out, 0, blockIdx.z, smf);
}

// ===========================================================================
// Fused attention, QT=256, NOW WITH 4 K/V BUFFERS: one barrier per TWO key
// tiles; tiles 2T and 2T+1 computed back-to-back in one unrolled region
// (independent S/exp/PV chains -> 2x ILP in the latency-critical region).
// Refill for tiles 2T+2,2T+3 issues right after the barrier into buffers
// last read in iter T-1 (sealed by this barrier). All-tf32, P full-fp32 in
// regs, B-frags via LDS.64 (K paired, V natural), bare ex2, softmax without
// max subtraction. Smem 143,360 B; 1 CTA/SM; 512 threads.
// ===========================================================================
#define QT 256
#define KTILE 64
#define NTILES (NN / KTILE)

#define AK2 136
#define AVS 72
#define KBW (32 * AK2)
#define VBW (64 * AVS)
#define OFF_K 0
#define OFF_V (4 * KBW)
#define ATTN_SMEM ((OFF_V + 4 * VBW) * 4)   // 143,360 bytes

__global__ void __launch_bounds__(512, 1) attn_mma_kernel(
    const float* __restrict__ Q, const float* __restrict__ K,
    const float* __restrict__ V, float* __restrict__ O)
{
    extern __shared__ float smf[];
    uint32_t* smw = (uint32_t*)smf;
    const uint32_t sb = smem_u32(smf);

    const int tid  = threadIdx.x;
    const int warp = tid >> 5;            // 0..15
    const int lane = tid & 31;
    const int j    = lane & 3;
    const int r    = lane >> 2;

    const int bid = blockIdx.x;
    const int q0  = (bid & 7) * QT;
    const int h   = (bid >> 3) & 3;
    const int b   = bid >> 5;
    const size_t base = (size_t)b * DD * NN + (size_t)h * NN;

    // K staging: thread covers 8 words of one pr-row
    const int kr   = tid >> 4;
    const int kseg = (tid & 15) * 8;
    const float* Kgc = K + (size_t)b * DD * NN + (size_t)h * 64 * NN
                     + (size_t)kr * 2 * NN + kseg;
    const uint32_t kaddr0 = sb + (OFF_K + kr * AK2 + kseg) * 4;
    // V staging: thread covers 8 keys of one dh-row
    const int vr   = tid >> 3;
    const int vseg = (tid & 7) * 8;
    const float* Vgc = V + base + (size_t)vr * HH * NN + vseg;
    const uint32_t vaddr0 = sb + (OFF_V + vr * AVS + vseg) * 4;

    // prologue: issue tiles 0 and 1 (buffers 0, 1)
#pragma unroll
    for (int t0 = 0; t0 < 2; t0++) {
#pragma unroll
        for (int i = 0; i < 2; i++) {
            cp16(kaddr0 + t0 * KBW * 4 + i * 16, Kgc + t0 * KTILE * 2 + i * 4);
            cp16(vaddr0 + t0 * VBW * 4 + i * 16, Vgc + t0 * KTILE + i * 4);
        }
        CP_COMMIT();
    }

    // Q A-fragments in registers (once)
    const int qrow = warp * 16 + r;
    uint32_t qa[8][4];
    {
        const float* Qg = Q + base + q0 + qrow;
#pragma unroll
        for (int kc = 0; kc < 8; kc++) {
            const float* p0 = Qg + (size_t)(kc * 8 + j) * HH * NN;
            const float* p1 = Qg + (size_t)(kc * 8 + j + 4) * HH * NN;
            qa[kc][0] = __float_as_uint(p0[0]);
            qa[kc][1] = __float_as_uint(p0[8]);
            qa[kc][2] = __float_as_uint(p1[0]);
            qa[kc][3] = __float_as_uint(p1[8]);
        }
    }

    float oacc[8][4];
#pragma unroll
    for (int nc = 0; nc < 8; nc++)
#pragma unroll
        for (int c = 0; c < 4; c++) oacc[nc][c] = 0.f;
    float rsA = 0.f, rsB = 0.f, rsC = 0.f, rsD = 0.f;

    for (int T = 0; T < NTILES / 2; T++) {
        CP_WAIT0();
        __syncthreads();   // tiles 2T,2T+1 visible; iter T-1 reads sealed

        // issue tiles 2T+2, 2T+3 into buffers (2T+2)&3, (2T+3)&3
        if (T + 1 < NTILES / 2) {
#pragma unroll
            for (int u = 0; u < 2; u++) {
                const int tn = 2 * T + 2 + u;
                const int nb = tn & 3;
                const int kn = tn * KTILE;
#pragma unroll
                for (int i = 0; i < 2; i++) {
                    cp16(kaddr0 + nb * KBW * 4 + i * 16, Kgc + kn * 2 + i * 4);
                    cp16(vaddr0 + nb * VBW * 4 + i * 16, Vgc + kn + i * 4);
                }
                CP_COMMIT();
            }
        }

        // compute tiles 2T and 2T+1 back-to-back (independent chains)
#pragma unroll
        for (int u = 0; u < 2; u++) {
            const int cur = (2 * T + u) & 3;
            const uint32_t* Kb = smw + OFF_K + cur * KBW;
            const uint32_t* Vb = smw + OFF_V + cur * VBW;

            // ---- S = Q . K^T ----
            float s[8][4];
#pragma unroll
            for (int nc = 0; nc < 8; nc++)
#pragma unroll
                for (int c = 0; c < 4; c++) s[nc][c] = 0.f;

#pragma unroll
            for (int kc = 0; kc < 8; kc++) {
                const int pr = kc * 4 + j;
#pragma unroll
                for (int nc = 0; nc < 8; nc++) {
                    const uint2 bb =
                        *(const uint2*)&Kb[pr * AK2 + (nc * 8 + r) * 2];
                    mma_tf32(s[nc], qa[kc][0], qa[kc][1], qa[kc][2], qa[kc][3],
                             bb.x, bb.y);
                }
            }

            // exp2 (log2e pre-folded); P stays full fp32 (HW truncates)
#pragma unroll
            for (int nc = 0; nc < 8; nc++) {
                const float e0 = ex2f(s[nc][0]);
                const float e1 = ex2f(s[nc][1]);
                const float e2 = ex2f(s[nc][2]);
                const float e3 = ex2f(s[nc][3]);
                if (nc & 1) { rsB += e0 + e1; rsD += e2 + e3; }
                else        { rsA += e0 + e1; rsC += e2 + e3; }
                s[nc][0] = e0; s[nc][1] = e1; s[nc][2] = e2; s[nc][3] = e3;
            }

            // ---- O += P . V ----
#pragma unroll
            for (int kc = 0; kc < 8; kc++) {
                const uint32_t a0 = __float_as_uint(s[kc][0]);
                const uint32_t a1 = __float_as_uint(s[kc][2]);
                const uint32_t a2 = __float_as_uint(s[kc][1]);
                const uint32_t a3 = __float_as_uint(s[kc][3]);
                const int kk = kc * 8 + 2 * j;
#pragma unroll
                for (int nc = 0; nc < 8; nc++) {
                    const uint2 vb =
                        *(const uint2*)&Vb[(nc * 8 + r) * AVS + kk];
                    mma_tf32(oacc[nc], a0, a1, a2, a3, vb.x, vb.y);
                }
            }
        }
    }

    float rs0 = rsA + rsB;
    float rs1 = rsC + rsD;
    rs0 += __shfl_xor_sync(0xffffffffu, rs0, 1);
    rs0 += __shfl_xor_sync(0xffffffffu, rs0, 2);
    rs1 += __shfl_xor_sync(0xffffffffu, rs1, 1);
    rs1 += __shfl_xor_sync(0xffffffffu, rs1, 2);
    const float inv0 = 1.0f / rs0;
    const float inv1 = 1.0f / rs1;

    // Stage normalized O as [q=256][dh] (stride 68), then store tf32-rounded
    __syncthreads();
#pragma unroll
    for (int nc = 0; nc < 8; nc++) {
        const int col = nc * 8 + 2 * j;
        smf[qrow * 68 + col]           = oacc[nc][0] * inv0;
        smf[qrow * 68 + col + 1]       = oacc[nc][1] * inv0;
        smf[(qrow + 8) * 68 + col]     = oacc[nc][2] * inv1;
        smf[(qrow + 8) * 68 + col + 1] = oacc[nc][3] * inv1;
    }
    __syncthreads();
    for (int idx = tid; idx < 64 * QT; idx += 512) {
        const int dh = idx >> 8;
        const int q  = idx & 255;
        O[base + (size_t)dh * HH * NN + q0 + q] =
            __uint_as_float(f2tf32(smf[q * 68 + dh]));
    }
}

// ===========================================================================
// Launch
// ===========================================================================
extern "C" void kernel_launch(void* const* d_in, const int* in_sizes, int n_in,
                              void* d_out, int out_size)
{
    const float* query = (const float*)d_in[0];
    const float* key   = (const float*)d_in[1];
    const float* value = (const float*)d_in[2];
    const float* Wq = (const float*)d_in[3];
    const float* bq = (const float*)d_in[4];
    const float* Wk = (const float*)d_in[5];
    const float* bk = (const float*)d_in[6];
    const float* Wv = (const float*)d_in[7];
    const float* bv = (const float*)d_in[8];
    const float* Wm = (const float*)d_in[9];
    const float* bm = (const float*)d_in[10];
    float* out = (float*)d_out;

    static float *pq = nullptr, *pk = nullptr, *pv = nullptr, *px = nullptr;
    static bool init_done = false;
    if (!init_done) {
        cudaGetSymbolAddress((void**)&pq, g_q);
        cudaGetSymbolAddress((void**)&pk, g_k);
        cudaGetSymbolAddress((void**)&pv, g_v);
        cudaGetSymbolAddress((void**)&px, g_x);
        cudaFuncSetAttribute(attn_mma_kernel,
                             cudaFuncAttributeMaxDynamicSharedMemorySize,
                             ATTN_SMEM);
        cudaFuncSetAttribute(proj_qkv_kernel,
                             cudaFuncAttributeMaxDynamicSharedMemorySize, PROJ_SMEM);
        cudaFuncSetAttribute(proj_out_kernel,
                             cudaFuncAttributeMaxDynamicSharedMemorySize, PROJ_SMEM);
        init_done = true;
    }

    prep_kernel<<<(BB * DD * NN / 4 + 255) / 256, 256>>>(
        query, key, value, Wq, Wk, Wv, Wm);

    dim3 qkvgrid(NN / 128, DD / 128, 3 * BB);   // (16, 2, 24) = 768 CTAs
    proj_qkv_kernel<<<qkvgrid, 256, PROJ_SMEM>>>(bq, bk, bv);

    attn_mma_kernel<<<BB * HH * (NN / QT), 512, ATTN_SMEM>>>(pq, pk, pv, px);

    dim3 ogrid(NN / 128, DD / 128, BB);         // (16, 2, 8) = 256 CTAs
    proj_out_kernel<<<ogrid, 256, PROJ_SMEM>>>(bm, out);
}